// round 8
// baseline (speedup 1.0000x reference)
#include <cuda_runtime.h>
#include <cuda_bf16.h>
#include <math.h>
#include <stdint.h>

// ---------------------------------------------------------------------------
// Problem constants
// ---------------------------------------------------------------------------
#define BATCH 8
#define SEQ   1024
#define DIM   768
#define HEADS 12
#define HDIM  64
#define ROWS  (BATCH * SEQ)     // 8192
#define QKVN  (3 * DIM)         // 2304
#define ATT_SCALE 0.125f
#define GK    768

// GEMM tiling: 128x128 tile, 4 warps of 64x64, BK=32
#define BM 128
#define BN 128
#define BK 32
#define NCH (GK / BK)
#define GEMM_THREADS 128
#define GS 40                   // smem row stride (bf16): 80B rows, conflict-free ldsm
#define MATB (BM * GS * 2)      // 10240
#define STAGEB (4 * MATB)       // 40960
#define SMEM_TOTAL (2 * STAGEB) // 81920

// Flash tiling: 256 q-rows per CTA, 8 warps of 32 rows
#define FS 72
#define FTB (64 * FS * 2)        // 9216
#define QTB2 (256 * FS * 2)      // 36864
#define FLASH_SMEM (2 * QTB2 + 2 * 4 * FTB)   // 147456

// ---------------------------------------------------------------------------
// Scratch device globals
// ---------------------------------------------------------------------------
__device__ __nv_bfloat16 g_xh[ROWS * DIM], g_xl[ROWS * DIM];
__device__ __nv_bfloat16 g_wqh[QKVN * DIM], g_wql[QKVN * DIM];
__device__ __nv_bfloat16 g_wph[DIM * DIM], g_wpl[DIM * DIM];
__device__ __nv_bfloat16 g_qh[BATCH * HEADS * SEQ * HDIM], g_ql[BATCH * HEADS * SEQ * HDIM];
__device__ __nv_bfloat16 g_kh[BATCH * HEADS * SEQ * HDIM], g_kl[BATCH * HEADS * SEQ * HDIM];
__device__ __nv_bfloat16 g_vth[BATCH * HEADS * HDIM * SEQ], g_vtl[BATCH * HEADS * HDIM * SEQ];
__device__ __nv_bfloat16 g_wah[ROWS * DIM], g_wal[ROWS * DIM];

// ---------------------------------------------------------------------------
// PTX helpers (plain sm_80-class)
// ---------------------------------------------------------------------------
__device__ __forceinline__ uint32_t smem_u32(const void* p) {
    uint32_t a;
    asm("{ .reg .u64 t; cvta.to.shared.u64 t, %1; cvt.u32.u64 %0, t; }" : "=r"(a) : "l"(p));
    return a;
}
__device__ __forceinline__ void cp16(uint32_t dst, const void* src) {
    asm volatile("cp.async.cg.shared.global [%0], [%1], 16;"
                 :: "r"(dst), "l"(__cvta_generic_to_global(src)) : "memory");
}
#define CP_COMMIT() asm volatile("cp.async.commit_group;" ::: "memory")
#define CP_WAIT(n)  asm volatile("cp.async.wait_group %0;" :: "n"(n) : "memory")

__device__ __forceinline__ void ldsm4(uint32_t addr, uint32_t* r) {
    asm volatile("ldmatrix.sync.aligned.m8n8.x4.shared.b16 {%0,%1,%2,%3}, [%4];"
                 : "=r"(r[0]), "=r"(r[1]), "=r"(r[2]), "=r"(r[3]) : "r"(addr));
}
__device__ __forceinline__ void mma_bf16(float* d, const uint32_t* a, const uint32_t* b) {
    asm volatile(
        "mma.sync.aligned.m16n8k16.row.col.f32.bf16.bf16.f32 "
        "{%0,%1,%2,%3}, {%4,%5,%6,%7}, {%8,%9}, {%0,%1,%2,%3};"
        : "+f"(d[0]), "+f"(d[1]), "+f"(d[2]), "+f"(d[3])
        : "r"(a[0]), "r"(a[1]), "r"(a[2]), "r"(a[3]), "r"(b[0]), "r"(b[1]));
}
__device__ __forceinline__ void bf_split(float v, __nv_bfloat16& h, __nv_bfloat16& l) {
    h = __float2bfloat16(v);
    l = __float2bfloat16(v - __bfloat162float(h));
}
__device__ __forceinline__ uint32_t pack2(__nv_bfloat16 a, __nv_bfloat16 b) {
    return (uint32_t)__bfloat16_as_ushort(a) | ((uint32_t)__bfloat16_as_ushort(b) << 16);
}

// ---------------------------------------------------------------------------
// Convert kernels
// ---------------------------------------------------------------------------
__global__ void split_x(const float* __restrict__ x) {
    int i = blockIdx.x * blockDim.x + threadIdx.x;
    float4 v = ((const float4*)x)[i];
    __nv_bfloat16 h0, h1, h2, h3, l0, l1, l2, l3;
    bf_split(v.x, h0, l0); bf_split(v.y, h1, l1);
    bf_split(v.z, h2, l2); bf_split(v.w, h3, l3);
    ushort4 H = { __bfloat16_as_ushort(h0), __bfloat16_as_ushort(h1),
                  __bfloat16_as_ushort(h2), __bfloat16_as_ushort(h3) };
    ushort4 L = { __bfloat16_as_ushort(l0), __bfloat16_as_ushort(l1),
                  __bfloat16_as_ushort(l2), __bfloat16_as_ushort(l3) };
    *(ushort4*)&g_xh[4 * i] = H;
    *(ushort4*)&g_xl[4 * i] = L;
}

template <int MODE>
__global__ void transpose_split(const float* __restrict__ w) {
    const int N = MODE == 0 ? QKVN : DIM;
    __nv_bfloat16* hi = MODE == 0 ? g_wqh : g_wph;
    __nv_bfloat16* lo = MODE == 0 ? g_wql : g_wpl;
    __shared__ float t[32][33];
    int n0 = blockIdx.x * 32, k0 = blockIdx.y * 32;
    int tx = threadIdx.x, ty = threadIdx.y;
#pragma unroll
    for (int j = 0; j < 4; ++j)
        t[ty + 8 * j][tx] = w[(size_t)(k0 + ty + 8 * j) * N + n0 + tx];
    __syncthreads();
#pragma unroll
    for (int j = 0; j < 4; ++j) {
        float v = t[tx][ty + 8 * j];
        __nv_bfloat16 h, l; bf_split(v, h, l);
        size_t o = (size_t)(n0 + ty + 8 * j) * GK + k0 + tx;
        hi[o] = h; lo[o] = l;
    }
}

// ---------------------------------------------------------------------------
// mma.sync bf16-split GEMM: 128 threads, 4 warps of 64x64
// MODE 0: -> q/k hi/lo [B,H,N,64], v hi/lo transposed [B,H,64,N]
// MODE 1: wa -> Cout (fp32)
// ---------------------------------------------------------------------------
template <int MODE>
__global__ __launch_bounds__(GEMM_THREADS, 2)
void tc_gemm(const float* __restrict__ bias, float* __restrict__ Cout) {
    extern __shared__ char smem[];
    const __nv_bfloat16* Ah = MODE == 0 ? g_xh : g_wah;
    const __nv_bfloat16* Al = MODE == 0 ? g_xl : g_wal;
    const __nv_bfloat16* Bh = MODE == 0 ? g_wqh : g_wph;
    const __nv_bfloat16* Bl = MODE == 0 ? g_wql : g_wpl;

    int tid = threadIdx.x;
    int bm = blockIdx.y * BM;
    int bn = blockIdx.x * BN;
    uint32_t sb = smem_u32(smem);

    // loader: one row (tid) per matrix, 4x16B chunks per row (BK=32 bf16 = 64B)
    const __nv_bfloat16* gsrc[4] = { Ah, Al, Bh, Bl };
    int grow[4] = { bm + tid, bm + tid, bn + tid, bn + tid };

    auto load_stage = [&](int s, int kc) {
        uint32_t base = sb + s * STAGEB + (uint32_t)tid * (GS * 2);
#pragma unroll
        for (int m = 0; m < 4; ++m) {
            const __nv_bfloat16* S = gsrc[m] + (size_t)grow[m] * GK + kc * BK;
            uint32_t dst = base + m * MATB;
#pragma unroll
            for (int c = 0; c < 4; ++c)
                cp16(dst + c * 16, S + c * 8);
        }
    };

    int wid = tid >> 5, lane = tid & 31;
    int wm = (wid >> 1) * 64;
    int wn = (wid & 1) * 64;
    int mat = lane >> 3, rr = lane & 7;
    int a_r = (mat & 1) * 8 + rr, a_c = (mat >> 1) * 8;
    int b_r = (mat >> 1) * 8 + rr, b_c = (mat & 1) * 8;

    float acc[4][8][4];
#pragma unroll
    for (int mf = 0; mf < 4; ++mf)
#pragma unroll
        for (int nf = 0; nf < 8; ++nf)
#pragma unroll
            for (int j = 0; j < 4; ++j) acc[mf][nf][j] = 0.0f;

    load_stage(0, 0);
    CP_COMMIT();

#pragma unroll 1
    for (int kc = 0; kc < NCH; ++kc) {
        if (kc + 1 < NCH) { load_stage((kc + 1) & 1, kc + 1); CP_COMMIT(); CP_WAIT(1); }
        else              { CP_WAIT(0); }
        __syncthreads();

        uint32_t st = sb + (kc & 1) * STAGEB;
        uint32_t sAh = st, sAl = st + MATB, sBh = st + 2 * MATB, sBl = st + 3 * MATB;

#pragma unroll
        for (int ks = 0; ks < BK; ks += 16) {
            uint32_t af[4][4], bh[4][4], bl[4][4];
#pragma unroll
            for (int ng = 0; ng < 4; ++ng) {
                uint32_t off = ((wn + ng * 16 + b_r) * GS + ks + b_c) * 2;
                ldsm4(sBh + off, bh[ng]);
                ldsm4(sBl + off, bl[ng]);
            }
#pragma unroll
            for (int mf = 0; mf < 4; ++mf)
                ldsm4(sAh + ((wm + mf * 16 + a_r) * GS + ks + a_c) * 2, af[mf]);
#pragma unroll
            for (int mf = 0; mf < 4; ++mf)
#pragma unroll
                for (int nf = 0; nf < 8; ++nf) {
                    mma_bf16(acc[mf][nf], af[mf], &bh[nf >> 1][(nf & 1) * 2]);
                    mma_bf16(acc[mf][nf], af[mf], &bl[nf >> 1][(nf & 1) * 2]);
                }
#pragma unroll
            for (int mf = 0; mf < 4; ++mf)
                ldsm4(sAl + ((wm + mf * 16 + a_r) * GS + ks + a_c) * 2, af[mf]);
#pragma unroll
            for (int mf = 0; mf < 4; ++mf)
#pragma unroll
                for (int nf = 0; nf < 8; ++nf)
                    mma_bf16(acc[mf][nf], af[mf], &bh[nf >> 1][(nf & 1) * 2]);
        }
        __syncthreads();
    }

    int g = lane >> 2, tg = lane & 3;
#pragma unroll
    for (int mf = 0; mf < 4; ++mf) {
#pragma unroll
        for (int nf = 0; nf < 8; ++nf) {
            int col = bn + wn + nf * 8 + tg * 2;
            float2 bv = *(const float2*)&bias[col];
#pragma unroll
            for (int half = 0; half < 2; ++half) {
                int row = bm + wm + mf * 16 + g + half * 8;
                float vx = acc[mf][nf][half * 2 + 0] + bv.x;
                float vy = acc[mf][nf][half * 2 + 1] + bv.y;
                if (MODE == 0) {
                    int which = col / DIM;
                    int rem = col - which * DIM;
                    int h = rem >> 6, d = rem & 63;
                    int b = row >> 10, n = row & 1023;
                    size_t hb = (size_t)(b * HEADS + h);
                    __nv_bfloat16 hx, lx, hy, ly;
                    bf_split(vx, hx, lx); bf_split(vy, hy, ly);
                    if (which == 2) {   // V: store transposed [B,H,64,N]
                        size_t o = (hb * HDIM + d) * SEQ + n;
                        g_vth[o] = hx; g_vtl[o] = lx;
                        g_vth[o + SEQ] = hy; g_vtl[o + SEQ] = ly;
                    } else {
                        size_t o = (hb * SEQ + n) * HDIM + d;
                        __nv_bfloat16* dh = which == 0 ? g_qh : g_kh;
                        __nv_bfloat16* dl = which == 0 ? g_ql : g_kl;
                        *(uint32_t*)&dh[o] = pack2(hx, hy);
                        *(uint32_t*)&dl[o] = pack2(lx, ly);
                    }
                } else {
                    float2 ov = { vx, vy };
                    *(float2*)&Cout[(size_t)row * DIM + col] = ov;
                }
            }
        }
    }
}

// ---------------------------------------------------------------------------
// Flash attention on HMMA, split bf16, 8 warps x 32 q-rows = 256 rows per CTA.
// ---------------------------------------------------------------------------
__global__ __launch_bounds__(256)
void flash_mma() {
    extern __shared__ char smem[];
    uint32_t sb = smem_u32(smem);
    int tid = threadIdx.x;
    int wid = tid >> 5, lane = tid & 31;
    int bh = blockIdx.y;
    int q0 = blockIdx.x * 256;

    const __nv_bfloat16* qh_src = g_qh + ((size_t)bh * SEQ + q0) * HDIM;
    const __nv_bfloat16* ql_src = g_ql + ((size_t)bh * SEQ + q0) * HDIM;
    const __nv_bfloat16* kh_src = g_kh + (size_t)bh * SEQ * HDIM;
    const __nv_bfloat16* kl_src = g_kl + (size_t)bh * SEQ * HDIM;
    const __nv_bfloat16* vh_src = g_vth + (size_t)bh * HDIM * SEQ;
    const __nv_bfloat16* vl_src = g_vtl + (size_t)bh * HDIM * SEQ;

    // ---- Q tile load: 256 rows x 64 bf16 (128 B/row!). One row per thread,
    // 8 x 16B chunks per row, hi at 0, lo at QTB2.  [R7 bug: only 4 chunks]
    {
        uint32_t d = sb + (uint32_t)tid * (FS * 2);
#pragma unroll
        for (int c = 0; c < 8; ++c) {
            cp16(d + c * 16, qh_src + (size_t)tid * HDIM + c * 8);
            cp16(d + QTB2 + c * 16, ql_src + (size_t)tid * HDIM + c * 8);
        }
    }

    // ---- stage loader: Kh,Kl,Vh,Vl 64x64 tiles (8 chunks per 128B row)
    int sr = tid >> 2, sc = (tid & 3) * 2;
    auto load_stage = [&](int s, int t) {
        uint32_t base = sb + 2 * QTB2 + s * 4 * FTB;
        const __nv_bfloat16* kh = kh_src + (size_t)(t * 64 + sr) * HDIM + sc * 8;
        const __nv_bfloat16* kl = kl_src + (size_t)(t * 64 + sr) * HDIM + sc * 8;
        const __nv_bfloat16* vh = vh_src + (size_t)sr * SEQ + t * 64 + sc * 8;
        const __nv_bfloat16* vl = vl_src + (size_t)sr * SEQ + t * 64 + sc * 8;
        uint32_t ro = (sr * FS) * 2 + sc * 16;
#pragma unroll
        for (int i = 0; i < 2; ++i) {
            cp16(base + ro + i * 16, kh + i * 8);
            cp16(base + FTB + ro + i * 16, kl + i * 8);
            cp16(base + 2 * FTB + ro + i * 16, vh + i * 8);
            cp16(base + 3 * FTB + ro + i * 16, vl + i * 8);
        }
    };

    int mat = lane >> 3, rr = lane & 7;
    int a_r = (mat & 1) * 8 + rr, a_c = (mat >> 1) * 8;
    int b_r = (mat >> 1) * 8 + rr, b_c = (mat & 1) * 8;
    int wq = wid * 32;
    int g = lane >> 2, tg = lane & 3;

    float o[2][8][4];
    float m0[2], m1[2], l0[2], l1[2];
#pragma unroll
    for (int mf = 0; mf < 2; ++mf) {
        m0[mf] = -1e30f; m1[mf] = -1e30f; l0[mf] = 0.0f; l1[mf] = 0.0f;
#pragma unroll
        for (int nf = 0; nf < 8; ++nf)
#pragma unroll
            for (int j = 0; j < 4; ++j) o[mf][nf][j] = 0.0f;
    }

    load_stage(0, 0);
    CP_COMMIT();

#pragma unroll 1
    for (int t = 0; t < SEQ / 64; ++t) {
        if (t + 1 < SEQ / 64) { load_stage((t + 1) & 1, t + 1); CP_COMMIT(); CP_WAIT(1); }
        else                  { CP_WAIT(0); }
        __syncthreads();

        uint32_t stK = sb + 2 * QTB2 + (t & 1) * 4 * FTB;
        uint32_t stV = stK + 2 * FTB;

        // ---- S = Q K^T (3 split passes), 2 m-frags of 16 rows
        float s[2][8][4];
#pragma unroll
        for (int mf = 0; mf < 2; ++mf)
#pragma unroll
            for (int nf = 0; nf < 8; ++nf)
#pragma unroll
                for (int j = 0; j < 4; ++j) s[mf][nf][j] = 0.0f;

#pragma unroll
        for (int kf = 0; kf < 4; ++kf) {
            uint32_t qh[2][4], ql[2][4];
#pragma unroll
            for (int mf = 0; mf < 2; ++mf) {
                uint32_t qoff = ((wq + mf * 16 + a_r) * FS + kf * 16 + a_c) * 2;
                ldsm4(sb + qoff, qh[mf]);
                ldsm4(sb + QTB2 + qoff, ql[mf]);
            }
#pragma unroll
            for (int ng = 0; ng < 4; ++ng) {
                uint32_t kh[4], kl[4];
                uint32_t off = ((ng * 16 + b_r) * FS + kf * 16 + b_c) * 2;
                ldsm4(stK + off, kh);
                ldsm4(stK + FTB + off, kl);
#pragma unroll
                for (int mf = 0; mf < 2; ++mf)
#pragma unroll
                    for (int half = 0; half < 2; ++half) {
                        float* ac = s[mf][ng * 2 + half];
                        mma_bf16(ac, qh[mf], &kh[half * 2]);
                        mma_bf16(ac, ql[mf], &kh[half * 2]);
                        mma_bf16(ac, qh[mf], &kl[half * 2]);
                    }
            }
        }

        // ---- softmax per m-frag (rows g and g+8; reduce over 4 lanes)
#pragma unroll
        for (int mf = 0; mf < 2; ++mf) {
            float mt0 = -1e30f, mt1 = -1e30f;
#pragma unroll
            for (int nf = 0; nf < 8; ++nf) {
#pragma unroll
                for (int j = 0; j < 4; ++j) s[mf][nf][j] *= ATT_SCALE;
                mt0 = fmaxf(mt0, fmaxf(s[mf][nf][0], s[mf][nf][1]));
                mt1 = fmaxf(mt1, fmaxf(s[mf][nf][2], s[mf][nf][3]));
            }
#pragma unroll
            for (int w = 1; w < 4; w <<= 1) {
                mt0 = fmaxf(mt0, __shfl_xor_sync(0xffffffffu, mt0, w));
                mt1 = fmaxf(mt1, __shfl_xor_sync(0xffffffffu, mt1, w));
            }
            float mn0 = fmaxf(m0[mf], mt0), mn1 = fmaxf(m1[mf], mt1);
            float c0 = __expf(m0[mf] - mn0), c1 = __expf(m1[mf] - mn1);
            m0[mf] = mn0; m1[mf] = mn1;
            float rs0 = 0.0f, rs1 = 0.0f;
#pragma unroll
            for (int nf = 0; nf < 8; ++nf) {
                s[mf][nf][0] = __expf(s[mf][nf][0] - mn0);
                s[mf][nf][1] = __expf(s[mf][nf][1] - mn0);
                s[mf][nf][2] = __expf(s[mf][nf][2] - mn1);
                s[mf][nf][3] = __expf(s[mf][nf][3] - mn1);
                rs0 += s[mf][nf][0] + s[mf][nf][1];
                rs1 += s[mf][nf][2] + s[mf][nf][3];
            }
#pragma unroll
            for (int w = 1; w < 4; w <<= 1) {
                rs0 += __shfl_xor_sync(0xffffffffu, rs0, w);
                rs1 += __shfl_xor_sync(0xffffffffu, rs1, w);
            }
            l0[mf] = l0[mf] * c0 + rs0;
            l1[mf] = l1[mf] * c1 + rs1;
#pragma unroll
            for (int nf = 0; nf < 8; ++nf) {
                o[mf][nf][0] *= c0; o[mf][nf][1] *= c0;
                o[mf][nf][2] *= c1; o[mf][nf][3] *= c1;
            }
        }

        // ---- O += P V (3 split passes); P A-frags packed from registers
#pragma unroll
        for (int kb = 0; kb < 4; ++kb) {
            uint32_t pah[2][4], pal[2][4];
#pragma unroll
            for (int mf = 0; mf < 2; ++mf)
#pragma unroll
                for (int q = 0; q < 2; ++q) {
                    float* sv = s[mf][2 * kb + q];
                    __nv_bfloat16 h0, lb0, h1, lb1, h2, lb2, h3, lb3;
                    bf_split(sv[0], h0, lb0); bf_split(sv[1], h1, lb1);
                    bf_split(sv[2], h2, lb2); bf_split(sv[3], h3, lb3);
                    pah[mf][q * 2 + 0] = pack2(h0, h1);  pah[mf][q * 2 + 1] = pack2(h2, h3);
                    pal[mf][q * 2 + 0] = pack2(lb0, lb1); pal[mf][q * 2 + 1] = pack2(lb2, lb3);
                }
#pragma unroll
            for (int ng = 0; ng < 4; ++ng) {
                uint32_t vh[4], vl[4];
                uint32_t off = ((ng * 16 + b_r) * FS + kb * 16 + b_c) * 2;
                ldsm4(stV + off, vh);
                ldsm4(stV + FTB + off, vl);
#pragma unroll
                for (int mf = 0; mf < 2; ++mf)
#pragma unroll
                    for (int half = 0; half < 2; ++half) {
                        float* ac = o[mf][ng * 2 + half];
                        mma_bf16(ac, pah[mf], &vh[half * 2]);
                        mma_bf16(ac, pal[mf], &vh[half * 2]);
                        mma_bf16(ac, pah[mf], &vl[half * 2]);
                    }
            }
        }
        __syncthreads();
    }

    // ---- epilogue: normalize, split, store wa hi/lo [B,N,768]
    int b_idx = bh / HEADS;
    int h = bh - b_idx * HEADS;
#pragma unroll
    for (int mf = 0; mf < 2; ++mf) {
        float inv0 = 1.0f / l0[mf], inv1 = 1.0f / l1[mf];
        size_t r0 = (size_t)(b_idx * SEQ + q0 + wq + mf * 16 + g) * DIM + h * HDIM;
        size_t r1 = r0 + 8 * DIM;
#pragma unroll
        for (int nf = 0; nf < 8; ++nf) {
            int col = nf * 8 + tg * 2;
            __nv_bfloat16 ha, la, hb, lb;
            bf_split(o[mf][nf][0] * inv0, ha, la); bf_split(o[mf][nf][1] * inv0, hb, lb);
            *(uint32_t*)&g_wah[r0 + col] = pack2(ha, hb);
            *(uint32_t*)&g_wal[r0 + col] = pack2(la, lb);
            bf_split(o[mf][nf][2] * inv1, ha, la); bf_split(o[mf][nf][3] * inv1, hb, lb);
            *(uint32_t*)&g_wah[r1 + col] = pack2(ha, hb);
            *(uint32_t*)&g_wal[r1 + col] = pack2(la, lb);
        }
    }
}

// ---------------------------------------------------------------------------
// Launch
// ---------------------------------------------------------------------------
extern "C" void kernel_launch(void* const* d_in, const int* in_sizes, int n_in,
                              void* d_out, int out_size)
{
    const float* x      = (const float*)d_in[0];
    const float* w_qkv  = (const float*)d_in[1];
    const float* b_qkv  = (const float*)d_in[2];
    const float* w_proj = (const float*)d_in[3];
    const float* b_proj = (const float*)d_in[4];
    float* out = (float*)d_out;

    cudaFuncSetAttribute(tc_gemm<0>, cudaFuncAttributeMaxDynamicSharedMemorySize, SMEM_TOTAL);
    cudaFuncSetAttribute(tc_gemm<1>, cudaFuncAttributeMaxDynamicSharedMemorySize, SMEM_TOTAL);
    cudaFuncSetAttribute(flash_mma, cudaFuncAttributeMaxDynamicSharedMemorySize, FLASH_SMEM);

    split_x<<<(ROWS * DIM / 4) / 256, 256>>>(x);
    transpose_split<0><<<dim3(QKVN / 32, DIM / 32), dim3(32, 8)>>>(w_qkv);
    transpose_split<1><<<dim3(DIM / 32, DIM / 32), dim3(32, 8)>>>(w_proj);

    tc_gemm<0><<<dim3(QKVN / BN, ROWS / BM), GEMM_THREADS, SMEM_TOTAL>>>(b_qkv, nullptr);

    flash_mma<<<dim3(SEQ / 256, BATCH * HEADS), 256, FLASH_SMEM>>>();

    tc_gemm<1><<<dim3(DIM / BN, ROWS / BM), GEMM_THREADS, SMEM_TOTAL>>>(b_proj, out);
}

// round 9
// speedup vs baseline: 1.1593x; 1.1593x over previous
#include <cuda_runtime.h>
#include <cuda_bf16.h>
#include <math.h>
#include <stdint.h>

// ---------------------------------------------------------------------------
// Problem constants
// ---------------------------------------------------------------------------
#define BATCH 8
#define SEQ   1024
#define DIM   768
#define HEADS 12
#define HDIM  64
#define ROWS  (BATCH * SEQ)     // 8192
#define QKVN  (3 * DIM)         // 2304
#define ATT_SCALE 0.125f
#define GK    768

// GEMM tiling (R6-proven: 256 threads, 8 warps of 64x32, BK=32)
#define BM 128
#define BN 128
#define BK 32
#define NCH (GK / BK)
#define GEMM_THREADS 256
#define GS 40                   // smem row stride (bf16): 80B rows, conflict-free ldsm
#define MATB (BM * GS * 2)
#define STAGEB (4 * MATB)
#define SMEM_TOTAL (2 * STAGEB) // 81920

// Flash tiling (R6-proven: 128 q-rows per CTA, 8 warps x 16 rows, 2 CTA/SM)
#define FS 72                    // (9r+c)%8 -> conflict-free
#define FTB (64 * FS * 2)        // 9216
#define QTB (128 * FS * 2)       // 18432
#define FLASH_SMEM (2 * QTB + 2 * 4 * FTB)   // 110592

// ---------------------------------------------------------------------------
// Scratch device globals
// ---------------------------------------------------------------------------
__device__ __nv_bfloat16 g_xh[ROWS * DIM], g_xl[ROWS * DIM];
__device__ __nv_bfloat16 g_wqh[QKVN * DIM], g_wql[QKVN * DIM];
__device__ __nv_bfloat16 g_wph[DIM * DIM], g_wpl[DIM * DIM];
__device__ __nv_bfloat16 g_qh[BATCH * HEADS * SEQ * HDIM], g_ql[BATCH * HEADS * SEQ * HDIM];
__device__ __nv_bfloat16 g_kh[BATCH * HEADS * SEQ * HDIM], g_kl[BATCH * HEADS * SEQ * HDIM];
__device__ __nv_bfloat16 g_vth[BATCH * HEADS * HDIM * SEQ], g_vtl[BATCH * HEADS * HDIM * SEQ]; // V^T
__device__ __nv_bfloat16 g_wah[ROWS * DIM], g_wal[ROWS * DIM];

// ---------------------------------------------------------------------------
// PTX helpers (plain sm_80-class)
// ---------------------------------------------------------------------------
__device__ __forceinline__ uint32_t smem_u32(const void* p) {
    uint32_t a;
    asm("{ .reg .u64 t; cvta.to.shared.u64 t, %1; cvt.u32.u64 %0, t; }" : "=r"(a) : "l"(p));
    return a;
}
__device__ __forceinline__ void cp16(uint32_t dst, const void* src) {
    asm volatile("cp.async.cg.shared.global [%0], [%1], 16;"
                 :: "r"(dst), "l"(__cvta_generic_to_global(src)) : "memory");
}
#define CP_COMMIT() asm volatile("cp.async.commit_group;" ::: "memory")
#define CP_WAIT(n)  asm volatile("cp.async.wait_group %0;" :: "n"(n) : "memory")

__device__ __forceinline__ void ldsm4(uint32_t addr, uint32_t* r) {
    asm volatile("ldmatrix.sync.aligned.m8n8.x4.shared.b16 {%0,%1,%2,%3}, [%4];"
                 : "=r"(r[0]), "=r"(r[1]), "=r"(r[2]), "=r"(r[3]) : "r"(addr));
}
__device__ __forceinline__ void mma_bf16(float* d, const uint32_t* a, const uint32_t* b) {
    asm volatile(
        "mma.sync.aligned.m16n8k16.row.col.f32.bf16.bf16.f32 "
        "{%0,%1,%2,%3}, {%4,%5,%6,%7}, {%8,%9}, {%0,%1,%2,%3};"
        : "+f"(d[0]), "+f"(d[1]), "+f"(d[2]), "+f"(d[3])
        : "r"(a[0]), "r"(a[1]), "r"(a[2]), "r"(a[3]), "r"(b[0]), "r"(b[1]));
}
__device__ __forceinline__ void bf_split(float v, __nv_bfloat16& h, __nv_bfloat16& l) {
    h = __float2bfloat16(v);
    l = __float2bfloat16(v - __bfloat162float(h));
}
__device__ __forceinline__ uint32_t pack2(__nv_bfloat16 a, __nv_bfloat16 b) {
    return (uint32_t)__bfloat16_as_ushort(a) | ((uint32_t)__bfloat16_as_ushort(b) << 16);
}

// ---------------------------------------------------------------------------
// Convert kernels
// ---------------------------------------------------------------------------
__global__ void split_x(const float* __restrict__ x) {
    int i = blockIdx.x * blockDim.x + threadIdx.x;
    float4 v = ((const float4*)x)[i];
    __nv_bfloat16 h0, h1, h2, h3, l0, l1, l2, l3;
    bf_split(v.x, h0, l0); bf_split(v.y, h1, l1);
    bf_split(v.z, h2, l2); bf_split(v.w, h3, l3);
    ushort4 H = { __bfloat16_as_ushort(h0), __bfloat16_as_ushort(h1),
                  __bfloat16_as_ushort(h2), __bfloat16_as_ushort(h3) };
    ushort4 L = { __bfloat16_as_ushort(l0), __bfloat16_as_ushort(l1),
                  __bfloat16_as_ushort(l2), __bfloat16_as_ushort(l3) };
    *(ushort4*)&g_xh[4 * i] = H;
    *(ushort4*)&g_xl[4 * i] = L;
}

template <int MODE>
__global__ void transpose_split(const float* __restrict__ w) {
    const int N = MODE == 0 ? QKVN : DIM;
    __nv_bfloat16* hi = MODE == 0 ? g_wqh : g_wph;
    __nv_bfloat16* lo = MODE == 0 ? g_wql : g_wpl;
    __shared__ float t[32][33];
    int n0 = blockIdx.x * 32, k0 = blockIdx.y * 32;
    int tx = threadIdx.x, ty = threadIdx.y;
#pragma unroll
    for (int j = 0; j < 4; ++j)
        t[ty + 8 * j][tx] = w[(size_t)(k0 + ty + 8 * j) * N + n0 + tx];
    __syncthreads();
#pragma unroll
    for (int j = 0; j < 4; ++j) {
        float v = t[tx][ty + 8 * j];
        __nv_bfloat16 h, l; bf_split(v, h, l);
        size_t o = (size_t)(n0 + ty + 8 * j) * GK + k0 + tx;
        hi[o] = h; lo[o] = l;
    }
}

// ---------------------------------------------------------------------------
// mma.sync bf16-split GEMM (R6 config: 256 thr, 8 warps 2x4, warp 64x32)
// MODE 0: -> q/k hi/lo [B,H,N,64], v hi/lo transposed [B,H,64,N]
// MODE 1: wa -> Cout (fp32)
// ---------------------------------------------------------------------------
template <int MODE>
__global__ __launch_bounds__(GEMM_THREADS, 2)
void tc_gemm(const float* __restrict__ bias, float* __restrict__ Cout) {
    extern __shared__ char smem[];
    const __nv_bfloat16* Ah = MODE == 0 ? g_xh : g_wah;
    const __nv_bfloat16* Al = MODE == 0 ? g_xl : g_wal;
    const __nv_bfloat16* Bh = MODE == 0 ? g_wqh : g_wph;
    const __nv_bfloat16* Bl = MODE == 0 ? g_wql : g_wpl;

    int tid = threadIdx.x;
    int bm = blockIdx.y * BM;
    int bn = blockIdx.x * BN;
    uint32_t sb = smem_u32(smem);

    int lrow = tid >> 1;
    int lch = (tid & 1) * 2;
    const __nv_bfloat16* gsrc[4] = { Ah, Al, Bh, Bl };
    int grow[4] = { bm + lrow, bm + lrow, bn + lrow, bn + lrow };

    auto load_stage = [&](int s, int kc) {
        uint32_t base = sb + s * STAGEB;
#pragma unroll
        for (int m = 0; m < 4; ++m) {
            const __nv_bfloat16* S = gsrc[m] + (size_t)grow[m] * GK + kc * BK + lch * 8;
            uint32_t dst = base + m * MATB + (lrow * GS + lch * 8) * 2;
            cp16(dst, S);
            cp16(dst + 16, S + 8);
        }
    };

    int wid = tid >> 5, lane = tid & 31;
    int wm = (wid >> 2) * 64;
    int wn = (wid & 3) * 32;
    int mat = lane >> 3, rr = lane & 7;
    int a_r = (mat & 1) * 8 + rr, a_c = (mat >> 1) * 8;
    int b_r = (mat >> 1) * 8 + rr, b_c = (mat & 1) * 8;

    float acc[4][4][4];
#pragma unroll
    for (int mf = 0; mf < 4; ++mf)
#pragma unroll
        for (int nf = 0; nf < 4; ++nf)
#pragma unroll
            for (int j = 0; j < 4; ++j) acc[mf][nf][j] = 0.0f;

    load_stage(0, 0);
    CP_COMMIT();

#pragma unroll 1
    for (int kc = 0; kc < NCH; ++kc) {
        if (kc + 1 < NCH) { load_stage((kc + 1) & 1, kc + 1); CP_COMMIT(); CP_WAIT(1); }
        else              { CP_WAIT(0); }
        __syncthreads();

        uint32_t st = sb + (kc & 1) * STAGEB;
        uint32_t sAh = st, sAl = st + MATB, sBh = st + 2 * MATB, sBl = st + 3 * MATB;

#pragma unroll
        for (int ks = 0; ks < BK; ks += 16) {
            uint32_t af[4][4], bh[2][4], bl[2][4];
#pragma unroll
            for (int ng = 0; ng < 2; ++ng) {
                uint32_t off = ((wn + ng * 16 + b_r) * GS + ks + b_c) * 2;
                ldsm4(sBh + off, bh[ng]);
                ldsm4(sBl + off, bl[ng]);
            }
#pragma unroll
            for (int mf = 0; mf < 4; ++mf)
                ldsm4(sAh + ((wm + mf * 16 + a_r) * GS + ks + a_c) * 2, af[mf]);
#pragma unroll
            for (int mf = 0; mf < 4; ++mf)
#pragma unroll
                for (int nf = 0; nf < 4; ++nf) {
                    mma_bf16(acc[mf][nf], af[mf], &bh[nf >> 1][(nf & 1) * 2]);
                    mma_bf16(acc[mf][nf], af[mf], &bl[nf >> 1][(nf & 1) * 2]);
                }
#pragma unroll
            for (int mf = 0; mf < 4; ++mf)
                ldsm4(sAl + ((wm + mf * 16 + a_r) * GS + ks + a_c) * 2, af[mf]);
#pragma unroll
            for (int mf = 0; mf < 4; ++mf)
#pragma unroll
                for (int nf = 0; nf < 4; ++nf)
                    mma_bf16(acc[mf][nf], af[mf], &bh[nf >> 1][(nf & 1) * 2]);
        }
        __syncthreads();
    }

    int g = lane >> 2, tg = lane & 3;
#pragma unroll
    for (int mf = 0; mf < 4; ++mf) {
#pragma unroll
        for (int nf = 0; nf < 4; ++nf) {
            int col = bn + wn + nf * 8 + tg * 2;
            float2 bv = *(const float2*)&bias[col];
#pragma unroll
            for (int half = 0; half < 2; ++half) {
                int row = bm + wm + mf * 16 + g + half * 8;
                float vx = acc[mf][nf][half * 2 + 0] + bv.x;
                float vy = acc[mf][nf][half * 2 + 1] + bv.y;
                if (MODE == 0) {
                    int which = col / DIM;
                    int rem = col - which * DIM;
                    int h = rem >> 6, d = rem & 63;
                    int b = row >> 10, n = row & 1023;
                    size_t hb = (size_t)(b * HEADS + h);
                    __nv_bfloat16 hx, lx, hy, ly;
                    bf_split(vx, hx, lx); bf_split(vy, hy, ly);
                    if (which == 2) {   // V: store transposed [B,H,64,N]
                        size_t o = (hb * HDIM + d) * SEQ + n;
                        g_vth[o] = hx; g_vtl[o] = lx;
                        g_vth[o + SEQ] = hy; g_vtl[o + SEQ] = ly;
                    } else {
                        size_t o = (hb * SEQ + n) * HDIM + d;
                        __nv_bfloat16* dh = which == 0 ? g_qh : g_kh;
                        __nv_bfloat16* dl = which == 0 ? g_ql : g_kl;
                        *(uint32_t*)&dh[o] = pack2(hx, hy);
                        *(uint32_t*)&dl[o] = pack2(lx, ly);
                    }
                } else {
                    float2 ov = { vx, vy };
                    *(float2*)&Cout[(size_t)row * DIM + col] = ov;
                }
            }
        }
    }
}

// ---------------------------------------------------------------------------
// Flash attention on HMMA (R6 config: 8 warps x 16 q-rows = 128 rows per CTA)
// S = Qh*Kh + Ql*Kh + Qh*Kl ; P split -> O = Ph*Vh + Pl*Vh + Ph*Vl
// ---------------------------------------------------------------------------
__global__ __launch_bounds__(256)
void flash_mma() {
    extern __shared__ char smem[];
    uint32_t sb = smem_u32(smem);
    int tid = threadIdx.x;
    int wid = tid >> 5, lane = tid & 31;
    int bh = blockIdx.y;
    int q0 = blockIdx.x * 128;

    const __nv_bfloat16* qh_src = g_qh + ((size_t)bh * SEQ + q0) * HDIM;
    const __nv_bfloat16* ql_src = g_ql + ((size_t)bh * SEQ + q0) * HDIM;
    const __nv_bfloat16* kh_src = g_kh + (size_t)bh * SEQ * HDIM;
    const __nv_bfloat16* kl_src = g_kl + (size_t)bh * SEQ * HDIM;
    const __nv_bfloat16* vh_src = g_vth + (size_t)bh * HDIM * SEQ;
    const __nv_bfloat16* vl_src = g_vtl + (size_t)bh * HDIM * SEQ;

    // ---- Q tile load (once): 128 rows x 64 (128B/row), hi at 0, lo at QTB
    {
        int qr = tid >> 1, qc = (tid & 1) * 4;
#pragma unroll
        for (int i = 0; i < 4; ++i) {
            uint32_t d = sb + (qr * FS) * 2 + (qc + i) * 16;
            cp16(d, qh_src + (size_t)qr * HDIM + (qc + i) * 8);
            cp16(d + QTB, ql_src + (size_t)qr * HDIM + (qc + i) * 8);
        }
    }

    // ---- stage loader: Kh,Kl,Vh,Vl 64x64 tiles
    int sr = tid >> 2, sc = (tid & 3) * 2;
    auto load_stage = [&](int s, int t) {
        uint32_t base = sb + 2 * QTB + s * 4 * FTB;
        const __nv_bfloat16* kh = kh_src + (size_t)(t * 64 + sr) * HDIM + sc * 8;
        const __nv_bfloat16* kl = kl_src + (size_t)(t * 64 + sr) * HDIM + sc * 8;
        const __nv_bfloat16* vh = vh_src + (size_t)sr * SEQ + t * 64 + sc * 8;
        const __nv_bfloat16* vl = vl_src + (size_t)sr * SEQ + t * 64 + sc * 8;
        uint32_t ro = (sr * FS) * 2 + sc * 16;
#pragma unroll
        for (int i = 0; i < 2; ++i) {
            cp16(base + ro + i * 16, kh + i * 8);
            cp16(base + FTB + ro + i * 16, kl + i * 8);
            cp16(base + 2 * FTB + ro + i * 16, vh + i * 8);
            cp16(base + 3 * FTB + ro + i * 16, vl + i * 8);
        }
    };

    int mat = lane >> 3, rr = lane & 7;
    int a_r = (mat & 1) * 8 + rr, a_c = (mat >> 1) * 8;
    int b_r = (mat >> 1) * 8 + rr, b_c = (mat & 1) * 8;
    int wq = wid * 16;
    int g = lane >> 2, tg = lane & 3;

    float o[8][4];
#pragma unroll
    for (int nf = 0; nf < 8; ++nf)
#pragma unroll
        for (int j = 0; j < 4; ++j) o[nf][j] = 0.0f;
    float m0 = -1e30f, m1 = -1e30f, l0 = 0.0f, l1 = 0.0f;

    load_stage(0, 0);
    CP_COMMIT();

#pragma unroll 1
    for (int t = 0; t < SEQ / 64; ++t) {
        if (t + 1 < SEQ / 64) { load_stage((t + 1) & 1, t + 1); CP_COMMIT(); CP_WAIT(1); }
        else                  { CP_WAIT(0); }
        __syncthreads();

        uint32_t stK = sb + 2 * QTB + (t & 1) * 4 * FTB;
        uint32_t stV = stK + 2 * FTB;

        // ---- S = Q K^T (3 split passes)
        float s[8][4];
#pragma unroll
        for (int nf = 0; nf < 8; ++nf)
#pragma unroll
            for (int j = 0; j < 4; ++j) s[nf][j] = 0.0f;

#pragma unroll
        for (int kf = 0; kf < 4; ++kf) {
            uint32_t qh[4], ql[4];
            uint32_t qoff = ((wq + a_r) * FS + kf * 16 + a_c) * 2;
            ldsm4(sb + qoff, qh);
            ldsm4(sb + QTB + qoff, ql);
#pragma unroll
            for (int ng = 0; ng < 4; ++ng) {
                uint32_t kh[4], kl[4];
                uint32_t off = ((ng * 16 + b_r) * FS + kf * 16 + b_c) * 2;
                ldsm4(stK + off, kh);
                ldsm4(stK + FTB + off, kl);
#pragma unroll
                for (int half = 0; half < 2; ++half) {
                    float* ac = s[ng * 2 + half];
                    mma_bf16(ac, qh, &kh[half * 2]);
                    mma_bf16(ac, ql, &kh[half * 2]);
                    mma_bf16(ac, qh, &kl[half * 2]);
                }
            }
        }

        // ---- softmax (registers): rows g (s[.][0,1]) and g+8 (s[.][2,3])
        float mt0 = -1e30f, mt1 = -1e30f;
#pragma unroll
        for (int nf = 0; nf < 8; ++nf) {
#pragma unroll
            for (int j = 0; j < 4; ++j) s[nf][j] *= ATT_SCALE;
            mt0 = fmaxf(mt0, fmaxf(s[nf][0], s[nf][1]));
            mt1 = fmaxf(mt1, fmaxf(s[nf][2], s[nf][3]));
        }
#pragma unroll
        for (int w = 1; w < 4; w <<= 1) {
            mt0 = fmaxf(mt0, __shfl_xor_sync(0xffffffffu, mt0, w));
            mt1 = fmaxf(mt1, __shfl_xor_sync(0xffffffffu, mt1, w));
        }
        float mn0 = fmaxf(m0, mt0), mn1 = fmaxf(m1, mt1);
        float c0 = __expf(m0 - mn0), c1 = __expf(m1 - mn1);
        m0 = mn0; m1 = mn1;
        float rs0 = 0.0f, rs1 = 0.0f;
#pragma unroll
        for (int nf = 0; nf < 8; ++nf) {
            s[nf][0] = __expf(s[nf][0] - mn0);
            s[nf][1] = __expf(s[nf][1] - mn0);
            s[nf][2] = __expf(s[nf][2] - mn1);
            s[nf][3] = __expf(s[nf][3] - mn1);
            rs0 += s[nf][0] + s[nf][1];
            rs1 += s[nf][2] + s[nf][3];
        }
#pragma unroll
        for (int w = 1; w < 4; w <<= 1) {
            rs0 += __shfl_xor_sync(0xffffffffu, rs0, w);
            rs1 += __shfl_xor_sync(0xffffffffu, rs1, w);
        }
        l0 = l0 * c0 + rs0;
        l1 = l1 * c1 + rs1;
#pragma unroll
        for (int nf = 0; nf < 8; ++nf) {
            o[nf][0] *= c0; o[nf][1] *= c0;
            o[nf][2] *= c1; o[nf][3] *= c1;
        }

        // ---- O += P V (3 split passes); P A-frags packed from registers
#pragma unroll
        for (int kb = 0; kb < 4; ++kb) {
            uint32_t pah[4], pal[4];
#pragma unroll
            for (int q = 0; q < 2; ++q) {
                float* sv = s[2 * kb + q];
                __nv_bfloat16 h0, l0b, h1, l1b, h2, l2b, h3, l3b;
                bf_split(sv[0], h0, l0b); bf_split(sv[1], h1, l1b);
                bf_split(sv[2], h2, l2b); bf_split(sv[3], h3, l3b);
                pah[q * 2 + 0] = pack2(h0, h1);  pah[q * 2 + 1] = pack2(h2, h3);
                pal[q * 2 + 0] = pack2(l0b, l1b); pal[q * 2 + 1] = pack2(l2b, l3b);
            }
#pragma unroll
            for (int ng = 0; ng < 4; ++ng) {
                uint32_t vh[4], vl[4];
                uint32_t off = ((ng * 16 + b_r) * FS + kb * 16 + b_c) * 2;
                ldsm4(stV + off, vh);
                ldsm4(stV + FTB + off, vl);
#pragma unroll
                for (int half = 0; half < 2; ++half) {
                    float* ac = o[ng * 2 + half];
                    mma_bf16(ac, pah, &vh[half * 2]);
                    mma_bf16(ac, pal, &vh[half * 2]);
                    mma_bf16(ac, pah, &vl[half * 2]);
                }
            }
        }
        __syncthreads();
    }

    // ---- epilogue: normalize, split, store wa hi/lo [B,N,768]
    float inv0 = 1.0f / l0, inv1 = 1.0f / l1;
    int b_idx = bh / HEADS;
    int h = bh - b_idx * HEADS;
    size_t r0 = (size_t)(b_idx * SEQ + q0 + wq + g) * DIM + h * HDIM;
    size_t r1 = r0 + 8 * DIM;
#pragma unroll
    for (int nf = 0; nf < 8; ++nf) {
        int col = nf * 8 + tg * 2;
        __nv_bfloat16 ha, la, hb, lb;
        bf_split(o[nf][0] * inv0, ha, la); bf_split(o[nf][1] * inv0, hb, lb);
        *(uint32_t*)&g_wah[r0 + col] = pack2(ha, hb);
        *(uint32_t*)&g_wal[r0 + col] = pack2(la, lb);
        bf_split(o[nf][2] * inv1, ha, la); bf_split(o[nf][3] * inv1, hb, lb);
        *(uint32_t*)&g_wah[r1 + col] = pack2(ha, hb);
        *(uint32_t*)&g_wal[r1 + col] = pack2(la, lb);
    }
}

// ---------------------------------------------------------------------------
// Launch
// ---------------------------------------------------------------------------
extern "C" void kernel_launch(void* const* d_in, const int* in_sizes, int n_in,
                              void* d_out, int out_size)
{
    const float* x      = (const float*)d_in[0];
    const float* w_qkv  = (const float*)d_in[1];
    const float* b_qkv  = (const float*)d_in[2];
    const float* w_proj = (const float*)d_in[3];
    const float* b_proj = (const float*)d_in[4];
    float* out = (float*)d_out;

    cudaFuncSetAttribute(tc_gemm<0>, cudaFuncAttributeMaxDynamicSharedMemorySize, SMEM_TOTAL);
    cudaFuncSetAttribute(tc_gemm<1>, cudaFuncAttributeMaxDynamicSharedMemorySize, SMEM_TOTAL);
    cudaFuncSetAttribute(flash_mma, cudaFuncAttributeMaxDynamicSharedMemorySize, FLASH_SMEM);

    split_x<<<(ROWS * DIM / 4) / 256, 256>>>(x);
    transpose_split<0><<<dim3(QKVN / 32, DIM / 32), dim3(32, 8)>>>(w_qkv);
    transpose_split<1><<<dim3(DIM / 32, DIM / 32), dim3(32, 8)>>>(w_proj);

    tc_gemm<0><<<dim3(QKVN / BN, ROWS / BM), GEMM_THREADS, SMEM_TOTAL>>>(b_qkv, nullptr);

    flash_mma<<<dim3(SEQ / 128, BATCH * HEADS), 256, FLASH_SMEM>>>();

    tc_gemm<1><<<dim3(DIM / BN, ROWS / BM), GEMM_THREADS, SMEM_TOTAL>>>(b_proj, out);
}

// round 10
// speedup vs baseline: 1.5650x; 1.3499x over previous
#include <cuda_runtime.h>
#include <cuda_fp16.h>
#include <math.h>
#include <stdint.h>

// ---------------------------------------------------------------------------
// Problem constants
// ---------------------------------------------------------------------------
#define BATCH 8
#define SEQ   1024
#define DIM   768
#define HEADS 12
#define HDIM  64
#define ROWS  (BATCH * SEQ)     // 8192
#define QKVN  (3 * DIM)         // 2304
#define ATT_SCALE 0.125f
#define GK    768

// GEMM tiling (R6-proven shape: 256 threads, 8 warps 2x4, warp 64x32, BK=32)
// fp16 2-pass: smem holds Ah, Al, Bh only.
#define BM 128
#define BN 128
#define BK 32
#define NCH (GK / BK)
#define GEMM_THREADS 256
#define GS 40                   // smem row stride (elems): 80B rows, conflict-free ldsm
#define MATB (BM * GS * 2)      // 10240
#define STAGEB (3 * MATB)       // Ah, Al, Bh = 30720
#define SMEM_TOTAL (2 * STAGEB) // 61440

// Flash tiling (R6-proven shape: 128 q-rows, 8 warps x 16 rows)
// fp16 2-pass: stages hold Kh, Vh only; Q hi+lo.
#define FS 72                    // (9r+c)%8 -> conflict-free
#define FTB (64 * FS * 2)        // 9216
#define QTB (128 * FS * 2)       // 18432
#define FLASH_SMEM (2 * QTB + 2 * 2 * FTB)   // 73728

// ---------------------------------------------------------------------------
// Scratch device globals (fp16)
// ---------------------------------------------------------------------------
__device__ __half g_xh[ROWS * DIM], g_xl[ROWS * DIM];          // x 2-term
__device__ __half g_wq[QKVN * GK];                              // w_qkv^T fp16
__device__ __half g_wp[DIM * GK];                               // w_proj^T fp16
__device__ __half g_qh[BATCH * HEADS * SEQ * HDIM], g_ql[BATCH * HEADS * SEQ * HDIM]; // Q 2-term
__device__ __half g_k[BATCH * HEADS * SEQ * HDIM];              // K fp16
__device__ __half g_vt[BATCH * HEADS * HDIM * SEQ];             // V^T fp16
__device__ __half g_wah[ROWS * DIM], g_wal[ROWS * DIM];         // wa 2-term

// ---------------------------------------------------------------------------
// PTX helpers (plain sm_80-class)
// ---------------------------------------------------------------------------
__device__ __forceinline__ uint32_t smem_u32(const void* p) {
    uint32_t a;
    asm("{ .reg .u64 t; cvta.to.shared.u64 t, %1; cvt.u32.u64 %0, t; }" : "=r"(a) : "l"(p));
    return a;
}
__device__ __forceinline__ void cp16(uint32_t dst, const void* src) {
    asm volatile("cp.async.cg.shared.global [%0], [%1], 16;"
                 :: "r"(dst), "l"(__cvta_generic_to_global(src)) : "memory");
}
#define CP_COMMIT() asm volatile("cp.async.commit_group;" ::: "memory")
#define CP_WAIT(n)  asm volatile("cp.async.wait_group %0;" :: "n"(n) : "memory")

__device__ __forceinline__ void ldsm4(uint32_t addr, uint32_t* r) {
    asm volatile("ldmatrix.sync.aligned.m8n8.x4.shared.b16 {%0,%1,%2,%3}, [%4];"
                 : "=r"(r[0]), "=r"(r[1]), "=r"(r[2]), "=r"(r[3]) : "r"(addr));
}
__device__ __forceinline__ void mma_f16(float* d, const uint32_t* a, const uint32_t* b) {
    asm volatile(
        "mma.sync.aligned.m16n8k16.row.col.f32.f16.f16.f32 "
        "{%0,%1,%2,%3}, {%4,%5,%6,%7}, {%8,%9}, {%0,%1,%2,%3};"
        : "+f"(d[0]), "+f"(d[1]), "+f"(d[2]), "+f"(d[3])
        : "r"(a[0]), "r"(a[1]), "r"(a[2]), "r"(a[3]), "r"(b[0]), "r"(b[1]));
}
__device__ __forceinline__ void h_split(float v, __half& h, __half& l) {
    h = __float2half(v);
    l = __float2half(v - __half2float(h));
}
__device__ __forceinline__ uint32_t pack2h(__half a, __half b) {
    return (uint32_t)__half_as_ushort(a) | ((uint32_t)__half_as_ushort(b) << 16);
}

// ---------------------------------------------------------------------------
// Convert kernels
// ---------------------------------------------------------------------------
__global__ void split_x(const float* __restrict__ x) {
    int i = blockIdx.x * blockDim.x + threadIdx.x;
    float4 v = ((const float4*)x)[i];
    __half h0, h1, h2, h3, l0, l1, l2, l3;
    h_split(v.x, h0, l0); h_split(v.y, h1, l1);
    h_split(v.z, h2, l2); h_split(v.w, h3, l3);
    uint2 H = { pack2h(h0, h1), pack2h(h2, h3) };
    uint2 L = { pack2h(l0, l1), pack2h(l2, l3) };
    *(uint2*)&g_xh[4 * i] = H;
    *(uint2*)&g_xl[4 * i] = L;
}

// w[K=768][N] -> w^T fp16 [N][768]
template <int MODE>   // 0: w_qkv (N=2304), 1: w_proj (N=768)
__global__ void transpose_split(const float* __restrict__ w) {
    const int N = MODE == 0 ? QKVN : DIM;
    __half* hi = MODE == 0 ? g_wq : g_wp;
    __shared__ float t[32][33];
    int n0 = blockIdx.x * 32, k0 = blockIdx.y * 32;
    int tx = threadIdx.x, ty = threadIdx.y;
#pragma unroll
    for (int j = 0; j < 4; ++j)
        t[ty + 8 * j][tx] = w[(size_t)(k0 + ty + 8 * j) * N + n0 + tx];
    __syncthreads();
#pragma unroll
    for (int j = 0; j < 4; ++j) {
        float v = t[tx][ty + 8 * j];
        hi[(size_t)(n0 + ty + 8 * j) * GK + k0 + tx] = __float2half(v);
    }
}

// ---------------------------------------------------------------------------
// fp16 2-pass GEMM: C = (Ah+Al)[M,768] @ Bh[N,768]^T + bias
// MODE 0: A=x, B=w_qkv^T -> Q 2-term, K fp16, V^T fp16
// MODE 1: A=wa, B=w_proj^T -> Cout (fp32)
// ---------------------------------------------------------------------------
template <int MODE>
__global__ __launch_bounds__(GEMM_THREADS, 2)
void tc_gemm(const float* __restrict__ bias, float* __restrict__ Cout) {
    extern __shared__ char smem[];
    const __half* Ah = MODE == 0 ? g_xh : g_wah;
    const __half* Al = MODE == 0 ? g_xl : g_wal;
    const __half* Bh = MODE == 0 ? g_wq : g_wp;

    int tid = threadIdx.x;
    int bm = blockIdx.y * BM;
    int bn = blockIdx.x * BN;
    uint32_t sb = smem_u32(smem);

    int lrow = tid >> 1;
    int lch = (tid & 1) * 2;
    const __half* gsrc[3] = { Ah, Al, Bh };
    int grow[3] = { bm + lrow, bm + lrow, bn + lrow };

    auto load_stage = [&](int s, int kc) {
        uint32_t base = sb + s * STAGEB;
#pragma unroll
        for (int m = 0; m < 3; ++m) {
            const __half* S = gsrc[m] + (size_t)grow[m] * GK + kc * BK + lch * 8;
            uint32_t dst = base + m * MATB + (lrow * GS + lch * 8) * 2;
            cp16(dst, S);
            cp16(dst + 16, S + 8);
        }
    };

    int wid = tid >> 5, lane = tid & 31;
    int wm = (wid >> 2) * 64;
    int wn = (wid & 3) * 32;
    int mat = lane >> 3, rr = lane & 7;
    int a_r = (mat & 1) * 8 + rr, a_c = (mat >> 1) * 8;
    int b_r = (mat >> 1) * 8 + rr, b_c = (mat & 1) * 8;

    float acc[4][4][4];
#pragma unroll
    for (int mf = 0; mf < 4; ++mf)
#pragma unroll
        for (int nf = 0; nf < 4; ++nf)
#pragma unroll
            for (int j = 0; j < 4; ++j) acc[mf][nf][j] = 0.0f;

    load_stage(0, 0);
    CP_COMMIT();

#pragma unroll 1
    for (int kc = 0; kc < NCH; ++kc) {
        if (kc + 1 < NCH) { load_stage((kc + 1) & 1, kc + 1); CP_COMMIT(); CP_WAIT(1); }
        else              { CP_WAIT(0); }
        __syncthreads();

        uint32_t st = sb + (kc & 1) * STAGEB;
        uint32_t sAh = st, sAl = st + MATB, sBh = st + 2 * MATB;

#pragma unroll
        for (int ks = 0; ks < BK; ks += 16) {
            uint32_t af[4][4], bh[2][4];
#pragma unroll
            for (int ng = 0; ng < 2; ++ng)
                ldsm4(sBh + ((wn + ng * 16 + b_r) * GS + ks + b_c) * 2, bh[ng]);
            // pass 1: Ah * Bh
#pragma unroll
            for (int mf = 0; mf < 4; ++mf)
                ldsm4(sAh + ((wm + mf * 16 + a_r) * GS + ks + a_c) * 2, af[mf]);
#pragma unroll
            for (int mf = 0; mf < 4; ++mf)
#pragma unroll
                for (int nf = 0; nf < 4; ++nf)
                    mma_f16(acc[mf][nf], af[mf], &bh[nf >> 1][(nf & 1) * 2]);
            // pass 2: Al * Bh
#pragma unroll
            for (int mf = 0; mf < 4; ++mf)
                ldsm4(sAl + ((wm + mf * 16 + a_r) * GS + ks + a_c) * 2, af[mf]);
#pragma unroll
            for (int mf = 0; mf < 4; ++mf)
#pragma unroll
                for (int nf = 0; nf < 4; ++nf)
                    mma_f16(acc[mf][nf], af[mf], &bh[nf >> 1][(nf & 1) * 2]);
        }
        __syncthreads();
    }

    int g = lane >> 2, tg = lane & 3;
#pragma unroll
    for (int mf = 0; mf < 4; ++mf) {
#pragma unroll
        for (int nf = 0; nf < 4; ++nf) {
            int col = bn + wn + nf * 8 + tg * 2;
            float2 bv = *(const float2*)&bias[col];
#pragma unroll
            for (int half = 0; half < 2; ++half) {
                int row = bm + wm + mf * 16 + g + half * 8;
                float vx = acc[mf][nf][half * 2 + 0] + bv.x;
                float vy = acc[mf][nf][half * 2 + 1] + bv.y;
                if (MODE == 0) {
                    int which = col / DIM;
                    int rem = col - which * DIM;
                    int h = rem >> 6, d = rem & 63;
                    int b = row >> 10, n = row & 1023;
                    size_t hb = (size_t)(b * HEADS + h);
                    if (which == 2) {          // V: fp16, transposed [B,H,64,N]
                        size_t o = (hb * HDIM + d) * SEQ + n;
                        g_vt[o] = __float2half(vx);
                        g_vt[o + SEQ] = __float2half(vy);
                    } else if (which == 1) {   // K: fp16 [B,H,N,64]
                        size_t o = (hb * SEQ + n) * HDIM + d;
                        *(uint32_t*)&g_k[o] = pack2h(__float2half(vx), __float2half(vy));
                    } else {                   // Q: 2-term fp16 [B,H,N,64]
                        size_t o = (hb * SEQ + n) * HDIM + d;
                        __half hx, lx, hy, ly;
                        h_split(vx, hx, lx); h_split(vy, hy, ly);
                        *(uint32_t*)&g_qh[o] = pack2h(hx, hy);
                        *(uint32_t*)&g_ql[o] = pack2h(lx, ly);
                    }
                } else {
                    float2 ov = { vx, vy };
                    *(float2*)&Cout[(size_t)row * DIM + col] = ov;
                }
            }
        }
    }
}

// ---------------------------------------------------------------------------
// Flash attention, fp16 2-pass: S = (Qh+Ql)*Kh ; O = (Ph+Pl)*Vh
// 8 warps x 16 q-rows = 128 rows per CTA.
// ---------------------------------------------------------------------------
__global__ __launch_bounds__(256)
void flash_mma() {
    extern __shared__ char smem[];
    uint32_t sb = smem_u32(smem);
    int tid = threadIdx.x;
    int wid = tid >> 5, lane = tid & 31;
    int bh = blockIdx.y;
    int q0 = blockIdx.x * 128;

    const __half* qh_src = g_qh + ((size_t)bh * SEQ + q0) * HDIM;
    const __half* ql_src = g_ql + ((size_t)bh * SEQ + q0) * HDIM;
    const __half* k_src  = g_k  + (size_t)bh * SEQ * HDIM;
    const __half* v_src  = g_vt + (size_t)bh * HDIM * SEQ;

    // ---- Q tile load (once): 128 rows x 64 (128 B/row), hi at 0, lo at QTB
    {
        int qr = tid >> 1, qc = (tid & 1) * 4;
#pragma unroll
        for (int i = 0; i < 4; ++i) {
            uint32_t d = sb + (qr * FS) * 2 + (qc + i) * 16;
            cp16(d, qh_src + (size_t)qr * HDIM + (qc + i) * 8);
            cp16(d + QTB, ql_src + (size_t)qr * HDIM + (qc + i) * 8);
        }
    }

    // ---- stage loader: Kh, Vh 64x64 tiles (128 B/row each)
    int sr = tid >> 2, sc = (tid & 3) * 2;
    auto load_stage = [&](int s, int t) {
        uint32_t base = sb + 2 * QTB + s * 2 * FTB;
        const __half* kp = k_src + (size_t)(t * 64 + sr) * HDIM + sc * 8;
        const __half* vp = v_src + (size_t)sr * SEQ + t * 64 + sc * 8;
        uint32_t ro = (sr * FS) * 2 + sc * 16;
#pragma unroll
        for (int i = 0; i < 2; ++i) {
            cp16(base + ro + i * 16, kp + i * 8);
            cp16(base + FTB + ro + i * 16, vp + i * 8);
        }
    };

    int mat = lane >> 3, rr = lane & 7;
    int a_r = (mat & 1) * 8 + rr, a_c = (mat >> 1) * 8;
    int b_r = (mat >> 1) * 8 + rr, b_c = (mat & 1) * 8;
    int wq = wid * 16;
    int g = lane >> 2, tg = lane & 3;

    float o[8][4];
#pragma unroll
    for (int nf = 0; nf < 8; ++nf)
#pragma unroll
        for (int j = 0; j < 4; ++j) o[nf][j] = 0.0f;
    float m0 = -1e30f, m1 = -1e30f, l0 = 0.0f, l1 = 0.0f;

    load_stage(0, 0);
    CP_COMMIT();

#pragma unroll 1
    for (int t = 0; t < SEQ / 64; ++t) {
        if (t + 1 < SEQ / 64) { load_stage((t + 1) & 1, t + 1); CP_COMMIT(); CP_WAIT(1); }
        else                  { CP_WAIT(0); }
        __syncthreads();

        uint32_t stK = sb + 2 * QTB + (t & 1) * 2 * FTB;
        uint32_t stV = stK + FTB;

        // ---- S = Q K^T (2 passes)
        float s[8][4];
#pragma unroll
        for (int nf = 0; nf < 8; ++nf)
#pragma unroll
            for (int j = 0; j < 4; ++j) s[nf][j] = 0.0f;

#pragma unroll
        for (int kf = 0; kf < 4; ++kf) {
            uint32_t qh[4], ql[4];
            uint32_t qoff = ((wq + a_r) * FS + kf * 16 + a_c) * 2;
            ldsm4(sb + qoff, qh);
            ldsm4(sb + QTB + qoff, ql);
#pragma unroll
            for (int ng = 0; ng < 4; ++ng) {
                uint32_t kh[4];
                ldsm4(stK + ((ng * 16 + b_r) * FS + kf * 16 + b_c) * 2, kh);
#pragma unroll
                for (int half = 0; half < 2; ++half) {
                    float* ac = s[ng * 2 + half];
                    mma_f16(ac, qh, &kh[half * 2]);
                    mma_f16(ac, ql, &kh[half * 2]);
                }
            }
        }

        // ---- softmax (registers): rows g (s[.][0,1]) and g+8 (s[.][2,3])
        float mt0 = -1e30f, mt1 = -1e30f;
#pragma unroll
        for (int nf = 0; nf < 8; ++nf) {
#pragma unroll
            for (int j = 0; j < 4; ++j) s[nf][j] *= ATT_SCALE;
            mt0 = fmaxf(mt0, fmaxf(s[nf][0], s[nf][1]));
            mt1 = fmaxf(mt1, fmaxf(s[nf][2], s[nf][3]));
        }
#pragma unroll
        for (int w = 1; w < 4; w <<= 1) {
            mt0 = fmaxf(mt0, __shfl_xor_sync(0xffffffffu, mt0, w));
            mt1 = fmaxf(mt1, __shfl_xor_sync(0xffffffffu, mt1, w));
        }
        float mn0 = fmaxf(m0, mt0), mn1 = fmaxf(m1, mt1);
        float c0 = __expf(m0 - mn0), c1 = __expf(m1 - mn1);
        m0 = mn0; m1 = mn1;
        float rs0 = 0.0f, rs1 = 0.0f;
#pragma unroll
        for (int nf = 0; nf < 8; ++nf) {
            s[nf][0] = __expf(s[nf][0] - mn0);
            s[nf][1] = __expf(s[nf][1] - mn0);
            s[nf][2] = __expf(s[nf][2] - mn1);
            s[nf][3] = __expf(s[nf][3] - mn1);
            rs0 += s[nf][0] + s[nf][1];
            rs1 += s[nf][2] + s[nf][3];
        }
#pragma unroll
        for (int w = 1; w < 4; w <<= 1) {
            rs0 += __shfl_xor_sync(0xffffffffu, rs0, w);
            rs1 += __shfl_xor_sync(0xffffffffu, rs1, w);
        }
        l0 = l0 * c0 + rs0;
        l1 = l1 * c1 + rs1;
#pragma unroll
        for (int nf = 0; nf < 8; ++nf) {
            o[nf][0] *= c0; o[nf][1] *= c0;
            o[nf][2] *= c1; o[nf][3] *= c1;
        }

        // ---- O += P V (2 passes); P A-frags packed from registers
#pragma unroll
        for (int kb = 0; kb < 4; ++kb) {
            uint32_t pah[4], pal[4];
#pragma unroll
            for (int q = 0; q < 2; ++q) {
                float* sv = s[2 * kb + q];
                __half h0, lb0, h1, lb1, h2, lb2, h3, lb3;
                h_split(sv[0], h0, lb0); h_split(sv[1], h1, lb1);
                h_split(sv[2], h2, lb2); h_split(sv[3], h3, lb3);
                pah[q * 2 + 0] = pack2h(h0, h1);  pah[q * 2 + 1] = pack2h(h2, h3);
                pal[q * 2 + 0] = pack2h(lb0, lb1); pal[q * 2 + 1] = pack2h(lb2, lb3);
            }
#pragma unroll
            for (int ng = 0; ng < 4; ++ng) {
                uint32_t vh[4];
                ldsm4(stV + ((ng * 16 + b_r) * FS + kb * 16 + b_c) * 2, vh);
#pragma unroll
                for (int half = 0; half < 2; ++half) {
                    float* ac = o[ng * 2 + half];
                    mma_f16(ac, pah, &vh[half * 2]);
                    mma_f16(ac, pal, &vh[half * 2]);
                }
            }
        }
        __syncthreads();
    }

    // ---- epilogue: normalize, split, store wa hi/lo [B,N,768] (fp16 2-term)
    float inv0 = 1.0f / l0, inv1 = 1.0f / l1;
    int b_idx = bh / HEADS;
    int h = bh - b_idx * HEADS;
    size_t r0 = (size_t)(b_idx * SEQ + q0 + wq + g) * DIM + h * HDIM;
    size_t r1 = r0 + 8 * DIM;
#pragma unroll
    for (int nf = 0; nf < 8; ++nf) {
        int col = nf * 8 + tg * 2;
        __half ha, la, hb, lb;
        h_split(o[nf][0] * inv0, ha, la); h_split(o[nf][1] * inv0, hb, lb);
        *(uint32_t*)&g_wah[r0 + col] = pack2h(ha, hb);
        *(uint32_t*)&g_wal[r0 + col] = pack2h(la, lb);
        h_split(o[nf][2] * inv1, ha, la); h_split(o[nf][3] * inv1, hb, lb);
        *(uint32_t*)&g_wah[r1 + col] = pack2h(ha, hb);
        *(uint32_t*)&g_wal[r1 + col] = pack2h(la, lb);
    }
}

// ---------------------------------------------------------------------------
// Launch
// ---------------------------------------------------------------------------
extern "C" void kernel_launch(void* const* d_in, const int* in_sizes, int n_in,
                              void* d_out, int out_size)
{
    const float* x      = (const float*)d_in[0];
    const float* w_qkv  = (const float*)d_in[1];
    const float* b_qkv  = (const float*)d_in[2];
    const float* w_proj = (const float*)d_in[3];
    const float* b_proj = (const float*)d_in[4];
    float* out = (float*)d_out;

    cudaFuncSetAttribute(tc_gemm<0>, cudaFuncAttributeMaxDynamicSharedMemorySize, SMEM_TOTAL);
    cudaFuncSetAttribute(tc_gemm<1>, cudaFuncAttributeMaxDynamicSharedMemorySize, SMEM_TOTAL);
    cudaFuncSetAttribute(flash_mma, cudaFuncAttributeMaxDynamicSharedMemorySize, FLASH_SMEM);

    split_x<<<(ROWS * DIM / 4) / 256, 256>>>(x);
    transpose_split<0><<<dim3(QKVN / 32, DIM / 32), dim3(32, 8)>>>(w_qkv);
    transpose_split<1><<<dim3(DIM / 32, DIM / 32), dim3(32, 8)>>>(w_proj);

    tc_gemm<0><<<dim3(QKVN / BN, ROWS / BM), GEMM_THREADS, SMEM_TOTAL>>>(b_qkv, nullptr);

    flash_mma<<<dim3(SEQ / 128, BATCH * HEADS), 256, FLASH_SMEM>>>();

    tc_gemm<1><<<dim3(DIM / BN, ROWS / BM), GEMM_THREADS, SMEM_TOTAL>>>(b_proj, out);
}

// round 11
// speedup vs baseline: 1.8162x; 1.1605x over previous
#include <cuda_runtime.h>
#include <cuda_fp16.h>
#include <math.h>
#include <stdint.h>

// ---------------------------------------------------------------------------
// Problem constants
// ---------------------------------------------------------------------------
#define BATCH 8
#define SEQ   1024
#define DIM   768
#define HEADS 12
#define HDIM  64
#define ROWS  (BATCH * SEQ)     // 8192
#define QKVN  (3 * DIM)         // 2304
#define ATT_SCALE 0.125f
#define GK    768

// GEMM tiling (256 threads, 8 warps 2x4, warp 64x32, BK=32)
#define BM 128
#define BN 128
#define BK 32
#define NCH (GK / BK)
#define GEMM_THREADS 256
#define GS 40                   // smem row stride (elems): 80B rows, conflict-free ldsm
#define MATB (BM * GS * 2)      // 10240

// Flash tiling (128 q-rows, 8 warps x 16 rows)
#define FS 72                    // (9r+c)%8 -> conflict-free
#define FTB (64 * FS * 2)        // 9216
#define QTB (128 * FS * 2)       // 18432
#define FLASH_SMEM (2 * QTB + 2 * 2 * FTB)   // 73728

// ---------------------------------------------------------------------------
// Scratch device globals (fp16)
// ---------------------------------------------------------------------------
__device__ __half g_xh[ROWS * DIM], g_xl[ROWS * DIM];          // x 2-term
__device__ __half g_wq[QKVN * GK];                              // w_qkv^T fp16
__device__ __half g_wp[DIM * GK];                               // w_proj^T fp16
__device__ __half g_qh[BATCH * HEADS * SEQ * HDIM], g_ql[BATCH * HEADS * SEQ * HDIM]; // Q 2-term
__device__ __half g_k[BATCH * HEADS * SEQ * HDIM];              // K fp16
__device__ __half g_vt[BATCH * HEADS * HDIM * SEQ];             // V^T fp16
__device__ __half g_wa[ROWS * DIM];                             // wa fp16 (1-term)

// ---------------------------------------------------------------------------
// PTX helpers (plain sm_80-class)
// ---------------------------------------------------------------------------
__device__ __forceinline__ uint32_t smem_u32(const void* p) {
    uint32_t a;
    asm("{ .reg .u64 t; cvta.to.shared.u64 t, %1; cvt.u32.u64 %0, t; }" : "=r"(a) : "l"(p));
    return a;
}
__device__ __forceinline__ void cp16(uint32_t dst, const void* src) {
    asm volatile("cp.async.cg.shared.global [%0], [%1], 16;"
                 :: "r"(dst), "l"(__cvta_generic_to_global(src)) : "memory");
}
#define CP_COMMIT() asm volatile("cp.async.commit_group;" ::: "memory")
#define CP_WAIT(n)  asm volatile("cp.async.wait_group %0;" :: "n"(n) : "memory")

__device__ __forceinline__ void ldsm4(uint32_t addr, uint32_t* r) {
    asm volatile("ldmatrix.sync.aligned.m8n8.x4.shared.b16 {%0,%1,%2,%3}, [%4];"
                 : "=r"(r[0]), "=r"(r[1]), "=r"(r[2]), "=r"(r[3]) : "r"(addr));
}
__device__ __forceinline__ void mma_f16(float* d, const uint32_t* a, const uint32_t* b) {
    asm volatile(
        "mma.sync.aligned.m16n8k16.row.col.f32.f16.f16.f32 "
        "{%0,%1,%2,%3}, {%4,%5,%6,%7}, {%8,%9}, {%0,%1,%2,%3};"
        : "+f"(d[0]), "+f"(d[1]), "+f"(d[2]), "+f"(d[3])
        : "r"(a[0]), "r"(a[1]), "r"(a[2]), "r"(a[3]), "r"(b[0]), "r"(b[1]));
}
__device__ __forceinline__ void h_split(float v, __half& h, __half& l) {
    h = __float2half(v);
    l = __float2half(v - __half2float(h));
}
__device__ __forceinline__ uint32_t pack2h(__half a, __half b) {
    return (uint32_t)__half_as_ushort(a) | ((uint32_t)__half_as_ushort(b) << 16);
}

// ---------------------------------------------------------------------------
// Convert kernels
// ---------------------------------------------------------------------------
__global__ void split_x(const float* __restrict__ x) {
    int i = blockIdx.x * blockDim.x + threadIdx.x;
    float4 v = ((const float4*)x)[i];
    __half h0, h1, h2, h3, l0, l1, l2, l3;
    h_split(v.x, h0, l0); h_split(v.y, h1, l1);
    h_split(v.z, h2, l2); h_split(v.w, h3, l3);
    uint2 H = { pack2h(h0, h1), pack2h(h2, h3) };
    uint2 L = { pack2h(l0, l1), pack2h(l2, l3) };
    *(uint2*)&g_xh[4 * i] = H;
    *(uint2*)&g_xl[4 * i] = L;
}

// w[K=768][N] -> w^T fp16 [N][768]
template <int MODE>   // 0: w_qkv (N=2304), 1: w_proj (N=768)
__global__ void transpose_split(const float* __restrict__ w) {
    const int N = MODE == 0 ? QKVN : DIM;
    __half* hi = MODE == 0 ? g_wq : g_wp;
    __shared__ float t[32][33];
    int n0 = blockIdx.x * 32, k0 = blockIdx.y * 32;
    int tx = threadIdx.x, ty = threadIdx.y;
#pragma unroll
    for (int j = 0; j < 4; ++j)
        t[ty + 8 * j][tx] = w[(size_t)(k0 + ty + 8 * j) * N + n0 + tx];
    __syncthreads();
#pragma unroll
    for (int j = 0; j < 4; ++j) {
        float v = t[tx][ty + 8 * j];
        hi[(size_t)(n0 + ty + 8 * j) * GK + k0 + tx] = __float2half(v);
    }
}

// ---------------------------------------------------------------------------
// fp16 GEMM: C = A[M,768] @ Bh[N,768]^T + bias
// MODE 0: A = x 2-term (2 passes) -> Q 2-term, K fp16, V^T fp16
// MODE 1: A = wa 1-term (1 pass)  -> Cout (fp32)
// ---------------------------------------------------------------------------
template <int MODE>
__global__ __launch_bounds__(GEMM_THREADS, 2)
void tc_gemm(const float* __restrict__ bias, float* __restrict__ Cout) {
    constexpr int NA = (MODE == 0) ? 2 : 1;       // A terms
    constexpr int NMAT = NA + 1;                  // matrices per stage
    constexpr uint32_t STB = NMAT * MATB;         // stage bytes
    extern __shared__ char smem[];
    const __half* Ah = MODE == 0 ? g_xh : g_wa;
    const __half* Bh = MODE == 0 ? g_wq : g_wp;

    int tid = threadIdx.x;
    int bm = blockIdx.y * BM;
    int bn = blockIdx.x * BN;
    uint32_t sb = smem_u32(smem);

    int lrow = tid >> 1;
    int lch = (tid & 1) * 2;
    const __half* gsrc[NMAT];
    int grow[NMAT];
    gsrc[0] = Ah;          grow[0] = bm + lrow;
    if (NA == 2) { gsrc[1] = g_xl; grow[1] = bm + lrow; }
    gsrc[NA] = Bh;         grow[NA] = bn + lrow;

    auto load_stage = [&](int s, int kc) {
        uint32_t base = sb + s * STB;
#pragma unroll
        for (int m = 0; m < NMAT; ++m) {
            const __half* S = gsrc[m] + (size_t)grow[m] * GK + kc * BK + lch * 8;
            uint32_t dst = base + m * MATB + (lrow * GS + lch * 8) * 2;
            cp16(dst, S);
            cp16(dst + 16, S + 8);
        }
    };

    int wid = tid >> 5, lane = tid & 31;
    int wm = (wid >> 2) * 64;
    int wn = (wid & 3) * 32;
    int mat = lane >> 3, rr = lane & 7;
    int a_r = (mat & 1) * 8 + rr, a_c = (mat >> 1) * 8;
    int b_r = (mat >> 1) * 8 + rr, b_c = (mat & 1) * 8;

    float acc[4][4][4];
#pragma unroll
    for (int mf = 0; mf < 4; ++mf)
#pragma unroll
        for (int nf = 0; nf < 4; ++nf)
#pragma unroll
            for (int j = 0; j < 4; ++j) acc[mf][nf][j] = 0.0f;

    load_stage(0, 0);
    CP_COMMIT();

#pragma unroll 1
    for (int kc = 0; kc < NCH; ++kc) {
        if (kc + 1 < NCH) { load_stage((kc + 1) & 1, kc + 1); CP_COMMIT(); CP_WAIT(1); }
        else              { CP_WAIT(0); }
        __syncthreads();

        uint32_t st = sb + (kc & 1) * STB;
        uint32_t sAh = st, sAl = st + MATB, sBh = st + NA * MATB;

#pragma unroll
        for (int ks = 0; ks < BK; ks += 16) {
            uint32_t af[4][4], bh[2][4];
#pragma unroll
            for (int ng = 0; ng < 2; ++ng)
                ldsm4(sBh + ((wn + ng * 16 + b_r) * GS + ks + b_c) * 2, bh[ng]);
            // pass 1: Ah * Bh
#pragma unroll
            for (int mf = 0; mf < 4; ++mf)
                ldsm4(sAh + ((wm + mf * 16 + a_r) * GS + ks + a_c) * 2, af[mf]);
#pragma unroll
            for (int mf = 0; mf < 4; ++mf)
#pragma unroll
                for (int nf = 0; nf < 4; ++nf)
                    mma_f16(acc[mf][nf], af[mf], &bh[nf >> 1][(nf & 1) * 2]);
            // pass 2: Al * Bh (MODE 0 only)
            if (NA == 2) {
#pragma unroll
                for (int mf = 0; mf < 4; ++mf)
                    ldsm4(sAl + ((wm + mf * 16 + a_r) * GS + ks + a_c) * 2, af[mf]);
#pragma unroll
                for (int mf = 0; mf < 4; ++mf)
#pragma unroll
                    for (int nf = 0; nf < 4; ++nf)
                        mma_f16(acc[mf][nf], af[mf], &bh[nf >> 1][(nf & 1) * 2]);
            }
        }
        __syncthreads();
    }

    int g = lane >> 2, tg = lane & 3;
#pragma unroll
    for (int mf = 0; mf < 4; ++mf) {
#pragma unroll
        for (int nf = 0; nf < 4; ++nf) {
            int col = bn + wn + nf * 8 + tg * 2;
            float2 bv = *(const float2*)&bias[col];
#pragma unroll
            for (int half = 0; half < 2; ++half) {
                int row = bm + wm + mf * 16 + g + half * 8;
                float vx = acc[mf][nf][half * 2 + 0] + bv.x;
                float vy = acc[mf][nf][half * 2 + 1] + bv.y;
                if (MODE == 0) {
                    int which = col / DIM;
                    int rem = col - which * DIM;
                    int h = rem >> 6, d = rem & 63;
                    int b = row >> 10, n = row & 1023;
                    size_t hb = (size_t)(b * HEADS + h);
                    if (which == 2) {          // V: fp16, transposed [B,H,64,N]
                        size_t o = (hb * HDIM + d) * SEQ + n;
                        g_vt[o] = __float2half(vx);
                        g_vt[o + SEQ] = __float2half(vy);
                    } else if (which == 1) {   // K: fp16 [B,H,N,64]
                        size_t o = (hb * SEQ + n) * HDIM + d;
                        *(uint32_t*)&g_k[o] = pack2h(__float2half(vx), __float2half(vy));
                    } else {                   // Q: 2-term fp16 [B,H,N,64]
                        size_t o = (hb * SEQ + n) * HDIM + d;
                        __half hx, lx, hy, ly;
                        h_split(vx, hx, lx); h_split(vy, hy, ly);
                        *(uint32_t*)&g_qh[o] = pack2h(hx, hy);
                        *(uint32_t*)&g_ql[o] = pack2h(lx, ly);
                    }
                } else {
                    float2 ov = { vx, vy };
                    *(float2*)&Cout[(size_t)row * DIM + col] = ov;
                }
            }
        }
    }
}

// ---------------------------------------------------------------------------
// Flash attention, fp16: S = (Qh+Ql)*Kh (2 passes) ; O = Ph*Vh (1 pass)
// 8 warps x 16 q-rows = 128 rows per CTA.
// ---------------------------------------------------------------------------
__global__ __launch_bounds__(256)
void flash_mma() {
    extern __shared__ char smem[];
    uint32_t sb = smem_u32(smem);
    int tid = threadIdx.x;
    int wid = tid >> 5, lane = tid & 31;
    int bh = blockIdx.y;
    int q0 = blockIdx.x * 128;

    const __half* qh_src = g_qh + ((size_t)bh * SEQ + q0) * HDIM;
    const __half* ql_src = g_ql + ((size_t)bh * SEQ + q0) * HDIM;
    const __half* k_src  = g_k  + (size_t)bh * SEQ * HDIM;
    const __half* v_src  = g_vt + (size_t)bh * HDIM * SEQ;

    // ---- Q tile load (once): 128 rows x 64 (128 B/row), hi at 0, lo at QTB
    {
        int qr = tid >> 1, qc = (tid & 1) * 4;
#pragma unroll
        for (int i = 0; i < 4; ++i) {
            uint32_t d = sb + (qr * FS) * 2 + (qc + i) * 16;
            cp16(d, qh_src + (size_t)qr * HDIM + (qc + i) * 8);
            cp16(d + QTB, ql_src + (size_t)qr * HDIM + (qc + i) * 8);
        }
    }

    // ---- stage loader: Kh, Vh 64x64 tiles (128 B/row each)
    int sr = tid >> 2, sc = (tid & 3) * 2;
    auto load_stage = [&](int s, int t) {
        uint32_t base = sb + 2 * QTB + s * 2 * FTB;
        const __half* kp = k_src + (size_t)(t * 64 + sr) * HDIM + sc * 8;
        const __half* vp = v_src + (size_t)sr * SEQ + t * 64 + sc * 8;
        uint32_t ro = (sr * FS) * 2 + sc * 16;
#pragma unroll
        for (int i = 0; i < 2; ++i) {
            cp16(base + ro + i * 16, kp + i * 8);
            cp16(base + FTB + ro + i * 16, vp + i * 8);
        }
    };

    int mat = lane >> 3, rr = lane & 7;
    int a_r = (mat & 1) * 8 + rr, a_c = (mat >> 1) * 8;
    int b_r = (mat >> 1) * 8 + rr, b_c = (mat & 1) * 8;
    int wq = wid * 16;
    int g = lane >> 2, tg = lane & 3;

    float o[8][4];
#pragma unroll
    for (int nf = 0; nf < 8; ++nf)
#pragma unroll
        for (int j = 0; j < 4; ++j) o[nf][j] = 0.0f;
    float m0 = -1e30f, m1 = -1e30f, l0 = 0.0f, l1 = 0.0f;

    load_stage(0, 0);
    CP_COMMIT();

#pragma unroll 1
    for (int t = 0; t < SEQ / 64; ++t) {
        if (t + 1 < SEQ / 64) { load_stage((t + 1) & 1, t + 1); CP_COMMIT(); CP_WAIT(1); }
        else                  { CP_WAIT(0); }
        __syncthreads();

        uint32_t stK = sb + 2 * QTB + (t & 1) * 2 * FTB;
        uint32_t stV = stK + FTB;

        // ---- S = Q K^T (2 passes)
        float s[8][4];
#pragma unroll
        for (int nf = 0; nf < 8; ++nf)
#pragma unroll
            for (int j = 0; j < 4; ++j) s[nf][j] = 0.0f;

#pragma unroll
        for (int kf = 0; kf < 4; ++kf) {
            uint32_t qh[4], ql[4];
            uint32_t qoff = ((wq + a_r) * FS + kf * 16 + a_c) * 2;
            ldsm4(sb + qoff, qh);
            ldsm4(sb + QTB + qoff, ql);
#pragma unroll
            for (int ng = 0; ng < 4; ++ng) {
                uint32_t kh[4];
                ldsm4(stK + ((ng * 16 + b_r) * FS + kf * 16 + b_c) * 2, kh);
#pragma unroll
                for (int half = 0; half < 2; ++half) {
                    float* ac = s[ng * 2 + half];
                    mma_f16(ac, qh, &kh[half * 2]);
                    mma_f16(ac, ql, &kh[half * 2]);
                }
            }
        }

        // ---- softmax (registers): rows g (s[.][0,1]) and g+8 (s[.][2,3])
        float mt0 = -1e30f, mt1 = -1e30f;
#pragma unroll
        for (int nf = 0; nf < 8; ++nf) {
#pragma unroll
            for (int j = 0; j < 4; ++j) s[nf][j] *= ATT_SCALE;
            mt0 = fmaxf(mt0, fmaxf(s[nf][0], s[nf][1]));
            mt1 = fmaxf(mt1, fmaxf(s[nf][2], s[nf][3]));
        }
#pragma unroll
        for (int w = 1; w < 4; w <<= 1) {
            mt0 = fmaxf(mt0, __shfl_xor_sync(0xffffffffu, mt0, w));
            mt1 = fmaxf(mt1, __shfl_xor_sync(0xffffffffu, mt1, w));
        }
        float mn0 = fmaxf(m0, mt0), mn1 = fmaxf(m1, mt1);
        float c0 = __expf(m0 - mn0), c1 = __expf(m1 - mn1);
        m0 = mn0; m1 = mn1;
        float rs0 = 0.0f, rs1 = 0.0f;
#pragma unroll
        for (int nf = 0; nf < 8; ++nf) {
            s[nf][0] = __expf(s[nf][0] - mn0);
            s[nf][1] = __expf(s[nf][1] - mn0);
            s[nf][2] = __expf(s[nf][2] - mn1);
            s[nf][3] = __expf(s[nf][3] - mn1);
            rs0 += s[nf][0] + s[nf][1];
            rs1 += s[nf][2] + s[nf][3];
        }
#pragma unroll
        for (int w = 1; w < 4; w <<= 1) {
            rs0 += __shfl_xor_sync(0xffffffffu, rs0, w);
            rs1 += __shfl_xor_sync(0xffffffffu, rs1, w);
        }
        l0 = l0 * c0 + rs0;
        l1 = l1 * c1 + rs1;
#pragma unroll
        for (int nf = 0; nf < 8; ++nf) {
            o[nf][0] *= c0; o[nf][1] *= c0;
            o[nf][2] *= c1; o[nf][3] *= c1;
        }

        // ---- O += P V (1 pass); P quantized to fp16 (post-softmax, linear)
#pragma unroll
        for (int kb = 0; kb < 4; ++kb) {
            uint32_t pah[4];
#pragma unroll
            for (int q = 0; q < 2; ++q) {
                float* sv = s[2 * kb + q];
                pah[q * 2 + 0] = pack2h(__float2half(sv[0]), __float2half(sv[1]));
                pah[q * 2 + 1] = pack2h(__float2half(sv[2]), __float2half(sv[3]));
            }
#pragma unroll
            for (int ng = 0; ng < 4; ++ng) {
                uint32_t vh[4];
                ldsm4(stV + ((ng * 16 + b_r) * FS + kb * 16 + b_c) * 2, vh);
#pragma unroll
                for (int half = 0; half < 2; ++half)
                    mma_f16(o[ng * 2 + half], pah, &vh[half * 2]);
            }
        }
        __syncthreads();
    }

    // ---- epilogue: normalize, store wa fp16 [B,N,768]
    float inv0 = 1.0f / l0, inv1 = 1.0f / l1;
    int b_idx = bh / HEADS;
    int h = bh - b_idx * HEADS;
    size_t r0 = (size_t)(b_idx * SEQ + q0 + wq + g) * DIM + h * HDIM;
    size_t r1 = r0 + 8 * DIM;
#pragma unroll
    for (int nf = 0; nf < 8; ++nf) {
        int col = nf * 8 + tg * 2;
        *(uint32_t*)&g_wa[r0 + col] =
            pack2h(__float2half(o[nf][0] * inv0), __float2half(o[nf][1] * inv0));
        *(uint32_t*)&g_wa[r1 + col] =
            pack2h(__float2half(o[nf][2] * inv1), __float2half(o[nf][3] * inv1));
    }
}

// ---------------------------------------------------------------------------
// Launch
// ---------------------------------------------------------------------------
extern "C" void kernel_launch(void* const* d_in, const int* in_sizes, int n_in,
                              void* d_out, int out_size)
{
    const float* x      = (const float*)d_in[0];
    const float* w_qkv  = (const float*)d_in[1];
    const float* b_qkv  = (const float*)d_in[2];
    const float* w_proj = (const float*)d_in[3];
    const float* b_proj = (const float*)d_in[4];
    float* out = (float*)d_out;

    const int SMEM_G0 = 2 * 3 * MATB;   // 61440: Ah, Al, Bh double-buffered
    const int SMEM_G1 = 2 * 2 * MATB;   // 40960: Ah, Bh double-buffered

    cudaFuncSetAttribute(tc_gemm<0>, cudaFuncAttributeMaxDynamicSharedMemorySize, SMEM_G0);
    cudaFuncSetAttribute(tc_gemm<1>, cudaFuncAttributeMaxDynamicSharedMemorySize, SMEM_G1);
    cudaFuncSetAttribute(flash_mma, cudaFuncAttributeMaxDynamicSharedMemorySize, FLASH_SMEM);

    split_x<<<(ROWS * DIM / 4) / 256, 256>>>(x);
    transpose_split<0><<<dim3(QKVN / 32, DIM / 32), dim3(32, 8)>>>(w_qkv);
    transpose_split<1><<<dim3(DIM / 32, DIM / 32), dim3(32, 8)>>>(w_proj);

    tc_gemm<0><<<dim3(QKVN / BN, ROWS / BM), GEMM_THREADS, SMEM_G0>>>(b_qkv, nullptr);

    flash_mma<<<dim3(SEQ / 128, BATCH * HEADS), 256, FLASH_SMEM>>>();

    tc_gemm<1><<<dim3(DIM / BN, ROWS / BM), GEMM_THREADS, SMEM_G1>>>(b_proj, out);
}